// round 4
// baseline (speedup 1.0000x reference)
#include <cuda_runtime.h>
#include <math.h>
#include <stdint.h>

#define B_ 2
#define T_ 2048
#define C_ 1024
#define H_ 16
#define HS_ 64
#define NQKV 1152  // 1024 q + 64 k + 64 v

// Scratch (allocation-free rule: __device__ globals)
__device__ float g_qkv[B_ * T_ * NQKV];    // fused projection output
__device__ float g_y[B_ * T_ * C_];

__device__ __forceinline__ uint32_t f2tf(float f) {
    uint32_t u;
    asm("cvt.rna.tf32.f32 %0, %1;" : "=r"(u) : "f"(f));
    return u;
}

__device__ __forceinline__ void mma_tf32(float c[4], const uint32_t* a, const uint32_t* b) {
    asm volatile(
        "mma.sync.aligned.m16n8k8.row.col.f32.tf32.tf32.f32 "
        "{%0,%1,%2,%3}, {%4,%5,%6,%7}, {%8,%9}, {%0,%1,%2,%3};"
        : "+f"(c[0]), "+f"(c[1]), "+f"(c[2]), "+f"(c[3])
        : "r"(a[0]), "r"(a[1]), "r"(a[2]), "r"(a[3]), "r"(b[0]), "r"(b[1]));
}

// C[m,n] = sum_k A[m,k] * W[n,k] (+bias), tf32 tensor cores, fragment-packed smem.
// BM=128, BK=32, BN=128. 256 threads = 8 warps (4m x 2n). Register-prefetch pipelined.
// QKV=true: W is the virtual concat Wq(1024) ‖ Wk(64) ‖ Wv(64), remapped per row.
template <bool BIAS, bool QKV>
__global__ __launch_bounds__(256) void gemm_tc(const float* __restrict__ A,
                                               const float* __restrict__ Wq,
                                               const float* __restrict__ Wk,
                                               const float* __restrict__ Wv,
                                               const float* __restrict__ bias,
                                               float* __restrict__ C,
                                               int N, int K) {
    __shared__ uint4 Asf[4][8][32];   // [kk][mtile16][lane] : A-frag uint4
    __shared__ uint2 Bsf[4][16][32];  // [kk][ntile8][lane]  : B-frag uint2
    uint32_t* asw = (uint32_t*)Asf;
    uint32_t* bsw = (uint32_t*)Bsf;

    int tid = threadIdx.x, lane = tid & 31, warp = tid >> 5;
    int wm = warp & 3, wn = warp >> 2;
    int bm = blockIdx.y * 128, bn = blockIdx.x * 128;
    int lr = tid >> 3, lc4 = (tid & 7) * 4;

    // Fragment scatter constants (fixed per thread)
    int skk = lc4 >> 3;
    int acomp = ((lr >> 3) & 1) | (((lc4 >> 2) & 1) << 1);
    int bslot = (lc4 >> 2) & 1;
    int lb = (lr & 7) * 4;

    float acc[2][8][4];
#pragma unroll
    for (int mt = 0; mt < 2; mt++)
#pragma unroll
        for (int j = 0; j < 8; j++)
#pragma unroll
            for (int e = 0; e < 4; e++) acc[mt][j][e] = 0.f;

    const float* arow[4];
    const float* wrow[4];
#pragma unroll
    for (int t = 0; t < 4; t++) {
        int ra = bm + lr + 32 * t;
        arow[t] = A + (size_t)ra * K + lc4;
        int rw = bn + lr + 32 * t;
        if (QKV)
            wrow[t] = (rw < 1024 ? Wq + (size_t)rw * K
                     : rw < 1088 ? Wk + (size_t)(rw - 1024) * K
                                 : Wv + (size_t)(rw - 1088) * K) + lc4;
        else
            wrow[t] = Wq + (size_t)rw * K + lc4;
    }

    float4 pa[4], pb[4];
#pragma unroll
    for (int t = 0; t < 4; t++) {
        pa[t] = *(const float4*)(arow[t]);
        pb[t] = *(const float4*)(wrow[t]);
    }

    for (int k0 = 0; k0 < K; k0 += 32) {
#pragma unroll
        for (int t = 0; t < 4; t++) {
            int amt = (lr >> 4) + 2 * t;
            uint32_t ai = ((skk * 8 + amt) * 32 + lb) * 4 + acomp;
            asw[ai + 0]  = f2tf(pa[t].x);
            asw[ai + 4]  = f2tf(pa[t].y);
            asw[ai + 8]  = f2tf(pa[t].z);
            asw[ai + 12] = f2tf(pa[t].w);
            int bjt = (lr >> 3) + 4 * t;
            uint32_t bi = ((skk * 16 + bjt) * 32 + lb) * 2 + bslot;
            bsw[bi + 0] = f2tf(pb[t].x);
            bsw[bi + 2] = f2tf(pb[t].y);
            bsw[bi + 4] = f2tf(pb[t].z);
            bsw[bi + 6] = f2tf(pb[t].w);
        }
        __syncthreads();
        if (k0 + 32 < K) {
#pragma unroll
            for (int t = 0; t < 4; t++) {
                pa[t] = *(const float4*)(arow[t] + k0 + 32);
                pb[t] = *(const float4*)(wrow[t] + k0 + 32);
            }
        }
#pragma unroll
        for (int kk = 0; kk < 4; kk++) {
            uint4 af[2];
            uint2 bf[8];
#pragma unroll
            for (int mt = 0; mt < 2; mt++) af[mt] = Asf[kk][wm * 2 + mt][lane];
#pragma unroll
            for (int j = 0; j < 8; j++) bf[j] = Bsf[kk][wn * 8 + j][lane];
#pragma unroll
            for (int mt = 0; mt < 2; mt++)
#pragma unroll
                for (int j = 0; j < 8; j++)
                    mma_tf32(acc[mt][j], (const uint32_t*)&af[mt], (const uint32_t*)&bf[j]);
        }
        __syncthreads();
    }

    int g = lane >> 2, q4 = lane & 3;
#pragma unroll
    for (int mt = 0; mt < 2; mt++)
#pragma unroll
        for (int j = 0; j < 8; j++) {
            int row = bm + wm * 32 + mt * 16 + g;
            int col = bn + wn * 64 + j * 8 + 2 * q4;
            float2 v0 = make_float2(acc[mt][j][0], acc[mt][j][1]);
            float2 v1 = make_float2(acc[mt][j][2], acc[mt][j][3]);
            if (BIAS) {
                float b0 = bias[col], b1 = bias[col + 1];
                v0.x += b0; v0.y += b1; v1.x += b0; v1.y += b1;
            }
            *(float2*)&C[(size_t)row * N + col] = v0;
            *(float2*)&C[(size_t)(row + 8) * N + col] = v1;
        }
}

// Flash-style causal MQA attention, tf32 tensor cores, fragment-packed K/V smem.
// 256 thr = 8 warps; each warp owns 16 query rows. 64-key tiles from fused qkv buffer.
// q remap quirk: q[b,h,t,:] = qkv[b, h*128 + t/16, (t%16)*64 .. +64).
__global__ __launch_bounds__(256, 2) void attn_tc(const float* __restrict__ qkv,
                                                  float* __restrict__ y) {
    __shared__ uint2 Ksf[8][8][32];  // [kk(dim8)][j(key8)][lane]
    __shared__ uint2 Vsf[8][8][32];  // [kk(key8)][j(dim8)][lane]
    uint32_t* ksw = (uint32_t*)Ksf;
    uint32_t* vsw = (uint32_t*)Vsf;

    int bid = blockIdx.x;
    int qt = 15 - (bid >> 5);  // longest blocks first (LPT)
    int bh = bid & 31;
    int b = bh >> 4, h = bh & 15;
    int tid = threadIdx.x, lane = tid & 31, warp = tid >> 5;
    int g = lane >> 2, q4 = lane & 3;
    int r0 = qt * 128 + warp * 16 + g;
    int r1 = r0 + 8;

    const float* base = qkv + (size_t)b * T_ * NQKV;

    // Q fragments (remapped), pre-scaled by hs^-0.5 = 0.125
    uint32_t qa[8][4];
#pragma unroll
    for (int kk = 0; kk < 8; kk++) {
        int c0 = kk * 8 + q4;
        size_t a0 = (size_t)(h * 128 + (r0 >> 4)) * NQKV + (r0 & 15) * 64;
        size_t a1 = (size_t)(h * 128 + (r1 >> 4)) * NQKV + (r1 & 15) * 64;
        qa[kk][0] = f2tf(0.125f * base[a0 + c0]);
        qa[kk][1] = f2tf(0.125f * base[a1 + c0]);
        qa[kk][2] = f2tf(0.125f * base[a0 + c0 + 4]);
        qa[kk][3] = f2tf(0.125f * base[a1 + c0 + 4]);
    }

    float o[8][4];
#pragma unroll
    for (int j = 0; j < 8; j++)
#pragma unroll
        for (int e = 0; e < 4; e++) o[j][e] = 0.f;
    float m0 = -INFINITY, m1 = -INFINITY, l0 = 0.f, l1 = 0.f;

    int nkt = qt * 2 + 2;
    int wrmin = qt * 128 + warp * 16;
    int wrmax = wrmin + 15;
    int srcA = (lane & ~3) | (q4 >> 1);
    int srcB = srcA + 2;
    bool sel = (q4 & 1) != 0;

    for (int kt = 0; kt < nkt; kt++) {
        __syncthreads();
#pragma unroll
        for (int t = 0; t < 4; t++) {
            int idx = tid + t * 256;
            int r = idx >> 4, c4 = (idx & 15) * 4;
            size_t row = (size_t)(kt * 64 + r) * NQKV;
            // K[key r][dim c] -> Ksf[c>>3][r>>3][(r&7)*4+(c&3)].slot(c>>2&1)
            float4 fk = *(const float4*)&base[row + 1024 + c4];
            uint32_t ki = (((c4 >> 3) * 8 + (r >> 3)) * 32 + (r & 7) * 4) * 2 + ((c4 >> 2) & 1);
            ksw[ki + 0] = f2tf(fk.x);
            ksw[ki + 2] = f2tf(fk.y);
            ksw[ki + 4] = f2tf(fk.z);
            ksw[ki + 6] = f2tf(fk.w);
            // V[key r][dim c] -> Vsf[r>>3][c>>3][(c&7)*4+(r&3)].slot(r>>2&1)
            float4 fv = *(const float4*)&base[row + 1088 + c4];
            uint32_t vi = (((r >> 3) * 8 + (c4 >> 3)) * 32 + (c4 & 7) * 4 + (r & 3)) * 2 +
                          ((r >> 2) & 1);
            vsw[vi + 0]  = f2tf(fv.x);
            vsw[vi + 8]  = f2tf(fv.y);
            vsw[vi + 16] = f2tf(fv.z);
            vsw[vi + 24] = f2tf(fv.w);
        }
        __syncthreads();
        int ktb = kt * 64;
        if (ktb > wrmax) continue;

        // S = Q K^T (pre-scaled)
        float s[8][4];
#pragma unroll
        for (int j = 0; j < 8; j++)
#pragma unroll
            for (int e = 0; e < 4; e++) s[j][e] = 0.f;
#pragma unroll
        for (int kk = 0; kk < 8; kk++) {
#pragma unroll
            for (int j = 0; j < 8; j++) {
                uint2 bf = Ksf[kk][j][lane];
                mma_tf32(s[j], qa[kk], (const uint32_t*)&bf);
            }
        }

        // mask + online softmax (s reused as float probabilities)
        bool needmask = (ktb + 63) > wrmin;
        float t0 = -INFINITY, t1 = -INFINITY;
#pragma unroll
        for (int j = 0; j < 8; j++) {
            if (needmask) {
                int tk = ktb + j * 8 + 2 * q4;
                if (tk > r0) s[j][0] = -INFINITY;
                if (tk + 1 > r0) s[j][1] = -INFINITY;
                if (tk > r1) s[j][2] = -INFINITY;
                if (tk + 1 > r1) s[j][3] = -INFINITY;
            }
            t0 = fmaxf(t0, fmaxf(s[j][0], s[j][1]));
            t1 = fmaxf(t1, fmaxf(s[j][2], s[j][3]));
        }
        t0 = fmaxf(t0, __shfl_xor_sync(0xffffffffu, t0, 1));
        t0 = fmaxf(t0, __shfl_xor_sync(0xffffffffu, t0, 2));
        t1 = fmaxf(t1, __shfl_xor_sync(0xffffffffu, t1, 1));
        t1 = fmaxf(t1, __shfl_xor_sync(0xffffffffu, t1, 2));
        float mn0 = fmaxf(m0, t0), mn1 = fmaxf(m1, t1);
        float cr0 = __expf(m0 - mn0), cr1 = __expf(m1 - mn1);
        m0 = mn0; m1 = mn1;
        l0 *= cr0; l1 *= cr1;
#pragma unroll
        for (int j = 0; j < 8; j++) {
            o[j][0] *= cr0; o[j][1] *= cr0;
            o[j][2] *= cr1; o[j][3] *= cr1;
        }
#pragma unroll
        for (int j = 0; j < 8; j++) {
            s[j][0] = __expf(s[j][0] - m0);
            s[j][1] = __expf(s[j][1] - m0);
            s[j][2] = __expf(s[j][2] - m1);
            s[j][3] = __expf(s[j][3] - m1);
            l0 += s[j][0] + s[j][1];
            l1 += s[j][2] + s[j][3];
        }

        // O += P V  (C-frag floats -> A-frag via quad shuffles, convert post-select)
#pragma unroll
        for (int kk = 0; kk < 8; kk++) {
            float x0 = __shfl_sync(0xffffffffu, s[kk][0], srcA);
            float x1 = __shfl_sync(0xffffffffu, s[kk][1], srcA);
            float x2 = __shfl_sync(0xffffffffu, s[kk][2], srcA);
            float x3 = __shfl_sync(0xffffffffu, s[kk][3], srcA);
            float y0 = __shfl_sync(0xffffffffu, s[kk][0], srcB);
            float y1 = __shfl_sync(0xffffffffu, s[kk][1], srcB);
            float y2 = __shfl_sync(0xffffffffu, s[kk][2], srcB);
            float y3 = __shfl_sync(0xffffffffu, s[kk][3], srcB);
            uint32_t pa[4];
            pa[0] = f2tf(sel ? x1 : x0);
            pa[1] = f2tf(sel ? x3 : x2);
            pa[2] = f2tf(sel ? y1 : y0);
            pa[3] = f2tf(sel ? y3 : y2);
#pragma unroll
            for (int j = 0; j < 8; j++) {
                uint2 bf = Vsf[kk][j][lane];
                mma_tf32(o[j], pa, (const uint32_t*)&bf);
            }
        }
    }

    l0 += __shfl_xor_sync(0xffffffffu, l0, 1);
    l0 += __shfl_xor_sync(0xffffffffu, l0, 2);
    l1 += __shfl_xor_sync(0xffffffffu, l1, 1);
    l1 += __shfl_xor_sync(0xffffffffu, l1, 2);
    float i0 = 1.f / l0, i1 = 1.f / l1;
    float* yb = y + (size_t)b * T_ * C_;
#pragma unroll
    for (int j = 0; j < 8; j++) {
        int col = h * 64 + j * 8 + 2 * q4;
        *(float2*)&yb[(size_t)r0 * C_ + col] = make_float2(o[j][0] * i0, o[j][1] * i0);
        *(float2*)&yb[(size_t)r1 * C_ + col] = make_float2(o[j][2] * i1, o[j][3] * i1);
    }
}

extern "C" void kernel_launch(void* const* d_in, const int* in_sizes, int n_in,
                              void* d_out, int out_size) {
    (void)in_sizes; (void)n_in; (void)out_size;
    const float* x  = (const float*)d_in[0];
    const float* Wk = (const float*)d_in[1];
    const float* Wv = (const float*)d_in[2];
    const float* Wq = (const float*)d_in[3];
    const float* Wp = (const float*)d_in[4];
    const float* bp = (const float*)d_in[5];
    float* out = (float*)d_out;

    float *qkvb, *yb;
    cudaGetSymbolAddress((void**)&qkvb, g_qkv);
    cudaGetSymbolAddress((void**)&yb, g_y);

    // Fused qkv projection with inline weight concat: [4096,1152]
    gemm_tc<false, true><<<dim3(9, 32), 256>>>(x, Wq, Wk, Wv, nullptr, qkvb, NQKV, 1024);
    // attention -> y [B,T,C] (head-transposed layout baked in)
    attn_tc<<<512, 256>>>(qkvb, yb);
    // out = y @ Wp.T + bp
    gemm_tc<true, false><<<dim3(8, 32), 256>>>(yb, Wp, nullptr, nullptr, bp, out, 1024, 1024);
}

// round 5
// speedup vs baseline: 2.2550x; 2.2550x over previous
#include <cuda_runtime.h>
#include <math.h>
#include <stdint.h>

#define B_ 2
#define T_ 2048
#define C_ 1024
#define H_ 16
#define HS_ 64
#define NQKV 1152  // 1024 q + 64 k + 64 v

// Scratch (allocation-free rule: __device__ globals)
__device__ float g_qkv[B_ * T_ * NQKV];    // fused projection output
__device__ float g_y[B_ * T_ * C_];

__device__ __forceinline__ uint32_t f2tf(float f) {
    uint32_t u;
    asm("cvt.rna.tf32.f32 %0, %1;" : "=r"(u) : "f"(f));
    return u;
}

__device__ __forceinline__ uint32_t smaddr(const void* p) {
    return (uint32_t)__cvta_generic_to_shared(p);
}

__device__ __forceinline__ void ldm_x4(uint32_t r[4], uint32_t a) {
    asm volatile("ldmatrix.sync.aligned.m8n8.x4.shared.b16 {%0,%1,%2,%3}, [%4];"
                 : "=r"(r[0]), "=r"(r[1]), "=r"(r[2]), "=r"(r[3]) : "r"(a));
}

__device__ __forceinline__ void mma_tf32(float c[4], const uint32_t* a, const uint32_t* b) {
    asm volatile(
        "mma.sync.aligned.m16n8k8.row.col.f32.tf32.tf32.f32 "
        "{%0,%1,%2,%3}, {%4,%5,%6,%7}, {%8,%9}, {%0,%1,%2,%3};"
        : "+f"(c[0]), "+f"(c[1]), "+f"(c[2]), "+f"(c[3])
        : "r"(a[0]), "r"(a[1]), "r"(a[2]), "r"(a[3]), "r"(b[0]), "r"(b[1]));
}

// C[m,n] = sum_k A[m,k] * W[n,k] (+bias), tf32 tensor cores, ldmatrix fragment loads.
// BM=128, BK=32, BN=128. 256 threads = 8 warps (4m x 2n). Register-prefetch pipelined.
// QKV=true: W is the virtual concat Wq(1024) ‖ Wk(64) ‖ Wv(64), remapped per row.
template <bool BIAS, bool QKV>
__global__ __launch_bounds__(256) void gemm_tc(const float* __restrict__ A,
                                               const float* __restrict__ Wq,
                                               const float* __restrict__ Wk,
                                               const float* __restrict__ Wv,
                                               const float* __restrict__ bias,
                                               float* __restrict__ C,
                                               int N, int K) {
    __shared__ uint32_t As[128][36];
    __shared__ uint32_t Bs[128][36];
    int tid = threadIdx.x, lane = tid & 31, warp = tid >> 5;
    int wm = warp & 3, wn = warp >> 2;
    int bm = blockIdx.y * 128, bn = blockIdx.x * 128;
    int lr = tid >> 3, lc4 = (tid & 7) * 4;

    // ldmatrix per-lane base addresses
    int aRow = wm * 32 + (lane & 15);
    int aCol = (lane >> 4) * 4;
    uint32_t abase = smaddr(&As[aRow][aCol]);
    int bRow = wn * 64 + (lane & 7) + ((lane >> 4) << 3);
    int bCol = ((lane >> 3) & 1) * 4;
    uint32_t bbase = smaddr(&Bs[bRow][bCol]);

    float acc[2][8][4];
#pragma unroll
    for (int mt = 0; mt < 2; mt++)
#pragma unroll
        for (int j = 0; j < 8; j++)
#pragma unroll
            for (int e = 0; e < 4; e++) acc[mt][j][e] = 0.f;

    const float* arow[4];
    const float* wrow[4];
#pragma unroll
    for (int t = 0; t < 4; t++) {
        int ra = bm + lr + 32 * t;
        arow[t] = A + (size_t)ra * K + lc4;
        int rw = bn + lr + 32 * t;
        if (QKV)
            wrow[t] = (rw < 1024 ? Wq + (size_t)rw * K
                     : rw < 1088 ? Wk + (size_t)(rw - 1024) * K
                                 : Wv + (size_t)(rw - 1088) * K) + lc4;
        else
            wrow[t] = Wq + (size_t)rw * K + lc4;
    }

    float4 pa[4], pb[4];
#pragma unroll
    for (int t = 0; t < 4; t++) {
        pa[t] = *(const float4*)(arow[t]);
        pb[t] = *(const float4*)(wrow[t]);
    }

    for (int k0 = 0; k0 < K; k0 += 32) {
#pragma unroll
        for (int t = 0; t < 4; t++) {
            *(uint4*)&As[lr + t * 32][lc4] =
                make_uint4(f2tf(pa[t].x), f2tf(pa[t].y), f2tf(pa[t].z), f2tf(pa[t].w));
            *(uint4*)&Bs[lr + t * 32][lc4] =
                make_uint4(f2tf(pb[t].x), f2tf(pb[t].y), f2tf(pb[t].z), f2tf(pb[t].w));
        }
        __syncthreads();
        if (k0 + 32 < K) {
#pragma unroll
            for (int t = 0; t < 4; t++) {
                pa[t] = *(const float4*)(arow[t] + k0 + 32);
                pb[t] = *(const float4*)(wrow[t] + k0 + 32);
            }
        }
#pragma unroll
        for (int kk = 0; kk < 4; kk++) {
            uint32_t af[2][4], bfr[4][4];
#pragma unroll
            for (int mt = 0; mt < 2; mt++)
                ldm_x4(af[mt], abase + (uint32_t)(mt * 16 * 36 + kk * 8) * 4u);
#pragma unroll
            for (int jp = 0; jp < 4; jp++)
                ldm_x4(bfr[jp], bbase + (uint32_t)(jp * 16 * 36 + kk * 8) * 4u);
#pragma unroll
            for (int mt = 0; mt < 2; mt++)
#pragma unroll
                for (int j = 0; j < 8; j++)
                    mma_tf32(acc[mt][j], af[mt], &bfr[j >> 1][(j & 1) * 2]);
        }
        __syncthreads();
    }

    int g = lane >> 2, q4 = lane & 3;
#pragma unroll
    for (int mt = 0; mt < 2; mt++)
#pragma unroll
        for (int j = 0; j < 8; j++) {
            int row = bm + wm * 32 + mt * 16 + g;
            int col = bn + wn * 64 + j * 8 + 2 * q4;
            float2 v0 = make_float2(acc[mt][j][0], acc[mt][j][1]);
            float2 v1 = make_float2(acc[mt][j][2], acc[mt][j][3]);
            if (BIAS) {
                float b0 = bias[col], b1 = bias[col + 1];
                v0.x += b0; v0.y += b1; v1.x += b0; v1.y += b1;
            }
            *(float2*)&C[(size_t)row * N + col] = v0;
            *(float2*)&C[(size_t)(row + 8) * N + col] = v1;
        }
}

// Flash-style causal MQA attention, tf32 tensor cores.
// 256 thr = 8 warps; each warp owns 16 query rows. 64-key tiles from fused qkv buffer.
// K frags via ldmatrix; V frags via j-grouped layout + LDS.128.
// q remap quirk: q[b,h,t,:] = qkv[b, h*128 + t/16, (t%16)*64 .. +64).
__global__ __launch_bounds__(256, 2) void attn_tc(const float* __restrict__ qkv,
                                                  float* __restrict__ y) {
    __shared__ uint32_t Ks[64][68];   // [key][dim]
    __shared__ uint32_t Vs2[64][72];  // [key][(dim&7)*8 + (dim>>3)]
    int bid = blockIdx.x;
    int qt = 15 - (bid >> 5);  // longest blocks first (LPT)
    int bh = bid & 31;
    int b = bh >> 4, h = bh & 15;
    int tid = threadIdx.x, lane = tid & 31, warp = tid >> 5;
    int g = lane >> 2, q4 = lane & 3;
    int r0 = qt * 128 + warp * 16 + g;
    int r1 = r0 + 8;

    const float* base = qkv + (size_t)b * T_ * NQKV;

    // ldmatrix base for K b-frags
    int kRow = (lane & 7) + ((lane >> 4) << 3);
    int kCol = ((lane >> 3) & 1) * 4;
    uint32_t kbase = smaddr(&Ks[kRow][kCol]);

    // Q fragments (remapped), pre-scaled by hs^-0.5 = 0.125
    uint32_t qa[8][4];
#pragma unroll
    for (int kk = 0; kk < 8; kk++) {
        int c0 = kk * 8 + q4;
        size_t a0 = (size_t)(h * 128 + (r0 >> 4)) * NQKV + (r0 & 15) * 64;
        size_t a1 = (size_t)(h * 128 + (r1 >> 4)) * NQKV + (r1 & 15) * 64;
        qa[kk][0] = f2tf(0.125f * base[a0 + c0]);
        qa[kk][1] = f2tf(0.125f * base[a1 + c0]);
        qa[kk][2] = f2tf(0.125f * base[a0 + c0 + 4]);
        qa[kk][3] = f2tf(0.125f * base[a1 + c0 + 4]);
    }

    float o[8][4];
#pragma unroll
    for (int j = 0; j < 8; j++)
#pragma unroll
        for (int e = 0; e < 4; e++) o[j][e] = 0.f;
    float m0 = -INFINITY, m1 = -INFINITY, l0 = 0.f, l1 = 0.f;

    int nkt = qt * 2 + 2;
    int wrmin = qt * 128 + warp * 16;
    int wrmax = wrmin + 15;
    int srcA = (lane & ~3) | (q4 >> 1);
    int srcB = srcA + 2;
    bool sel = (q4 & 1) != 0;

    for (int kt = 0; kt < nkt; kt++) {
        __syncthreads();
#pragma unroll
        for (int t = 0; t < 4; t++) {
            int idx = tid + t * 256;
            int r = idx >> 4, c4 = (idx & 15) * 4;
            size_t row = (size_t)(kt * 64 + r) * NQKV;
            float4 fk = *(const float4*)&base[row + 1024 + c4];
            *(uint4*)&Ks[r][c4] = make_uint4(f2tf(fk.x), f2tf(fk.y), f2tf(fk.z), f2tf(fk.w));
            float4 fv = *(const float4*)&base[row + 1088 + c4];
            int c7 = c4 & 7, cj = c4 >> 3;
            Vs2[r][(c7 + 0) * 8 + cj] = f2tf(fv.x);
            Vs2[r][(c7 + 1) * 8 + cj] = f2tf(fv.y);
            Vs2[r][(c7 + 2) * 8 + cj] = f2tf(fv.z);
            Vs2[r][(c7 + 3) * 8 + cj] = f2tf(fv.w);
        }
        __syncthreads();
        int ktb = kt * 64;
        if (ktb > wrmax) continue;

        // S = Q K^T (pre-scaled)
        float s[8][4];
#pragma unroll
        for (int j = 0; j < 8; j++)
#pragma unroll
            for (int e = 0; e < 4; e++) s[j][e] = 0.f;
#pragma unroll
        for (int kk = 0; kk < 8; kk++) {
            uint32_t kf[4][4];
#pragma unroll
            for (int jp = 0; jp < 4; jp++)
                ldm_x4(kf[jp], kbase + (uint32_t)(jp * 16 * 68 + kk * 8) * 4u);
#pragma unroll
            for (int j = 0; j < 8; j++)
                mma_tf32(s[j], qa[kk], &kf[j >> 1][(j & 1) * 2]);
        }

        // mask + online softmax (s reused as float probabilities)
        bool needmask = (ktb + 63) > wrmin;
        float t0 = -INFINITY, t1 = -INFINITY;
#pragma unroll
        for (int j = 0; j < 8; j++) {
            if (needmask) {
                int tk = ktb + j * 8 + 2 * q4;
                if (tk > r0) s[j][0] = -INFINITY;
                if (tk + 1 > r0) s[j][1] = -INFINITY;
                if (tk > r1) s[j][2] = -INFINITY;
                if (tk + 1 > r1) s[j][3] = -INFINITY;
            }
            t0 = fmaxf(t0, fmaxf(s[j][0], s[j][1]));
            t1 = fmaxf(t1, fmaxf(s[j][2], s[j][3]));
        }
        t0 = fmaxf(t0, __shfl_xor_sync(0xffffffffu, t0, 1));
        t0 = fmaxf(t0, __shfl_xor_sync(0xffffffffu, t0, 2));
        t1 = fmaxf(t1, __shfl_xor_sync(0xffffffffu, t1, 1));
        t1 = fmaxf(t1, __shfl_xor_sync(0xffffffffu, t1, 2));
        float mn0 = fmaxf(m0, t0), mn1 = fmaxf(m1, t1);
        float cr0 = __expf(m0 - mn0), cr1 = __expf(m1 - mn1);
        m0 = mn0; m1 = mn1;
        l0 *= cr0; l1 *= cr1;
#pragma unroll
        for (int j = 0; j < 8; j++) {
            o[j][0] *= cr0; o[j][1] *= cr0;
            o[j][2] *= cr1; o[j][3] *= cr1;
        }
#pragma unroll
        for (int j = 0; j < 8; j++) {
            s[j][0] = __expf(s[j][0] - m0);
            s[j][1] = __expf(s[j][1] - m0);
            s[j][2] = __expf(s[j][2] - m1);
            s[j][3] = __expf(s[j][3] - m1);
            l0 += s[j][0] + s[j][1];
            l1 += s[j][2] + s[j][3];
        }

        // O += P V  (C-frag floats -> A-frag via quad shuffles; V b-frags via LDS.128)
#pragma unroll
        for (int kk = 0; kk < 8; kk++) {
            float x0 = __shfl_sync(0xffffffffu, s[kk][0], srcA);
            float x1 = __shfl_sync(0xffffffffu, s[kk][1], srcA);
            float x2 = __shfl_sync(0xffffffffu, s[kk][2], srcA);
            float x3 = __shfl_sync(0xffffffffu, s[kk][3], srcA);
            float y0 = __shfl_sync(0xffffffffu, s[kk][0], srcB);
            float y1 = __shfl_sync(0xffffffffu, s[kk][1], srcB);
            float y2 = __shfl_sync(0xffffffffu, s[kk][2], srcB);
            float y3 = __shfl_sync(0xffffffffu, s[kk][3], srcB);
            uint32_t pa[4];
            pa[0] = f2tf(sel ? x1 : x0);
            pa[1] = f2tf(sel ? x3 : x2);
            pa[2] = f2tf(sel ? y1 : y0);
            pa[3] = f2tf(sel ? y3 : y2);
            const uint4* v0p = (const uint4*)&Vs2[kk * 8 + q4][g * 8];
            const uint4* v1p = (const uint4*)&Vs2[kk * 8 + q4 + 4][g * 8];
            uint4 b0lo = v0p[0], b0hi = v0p[1];
            uint4 b1lo = v1p[0], b1hi = v1p[1];
            uint32_t vb0[8] = {b0lo.x, b0lo.y, b0lo.z, b0lo.w, b0hi.x, b0hi.y, b0hi.z, b0hi.w};
            uint32_t vb1[8] = {b1lo.x, b1lo.y, b1lo.z, b1lo.w, b1hi.x, b1hi.y, b1hi.z, b1hi.w};
#pragma unroll
            for (int j = 0; j < 8; j++) {
                uint32_t bf[2] = {vb0[j], vb1[j]};
                mma_tf32(o[j], pa, bf);
            }
        }
    }

    l0 += __shfl_xor_sync(0xffffffffu, l0, 1);
    l0 += __shfl_xor_sync(0xffffffffu, l0, 2);
    l1 += __shfl_xor_sync(0xffffffffu, l1, 1);
    l1 += __shfl_xor_sync(0xffffffffu, l1, 2);
    float i0 = 1.f / l0, i1 = 1.f / l1;
    float* yb = y + (size_t)b * T_ * C_;
#pragma unroll
    for (int j = 0; j < 8; j++) {
        int col = h * 64 + j * 8 + 2 * q4;
        *(float2*)&yb[(size_t)r0 * C_ + col] = make_float2(o[j][0] * i0, o[j][1] * i0);
        *(float2*)&yb[(size_t)r1 * C_ + col] = make_float2(o[j][2] * i1, o[j][3] * i1);
    }
}

extern "C" void kernel_launch(void* const* d_in, const int* in_sizes, int n_in,
                              void* d_out, int out_size) {
    (void)in_sizes; (void)n_in; (void)out_size;
    const float* x  = (const float*)d_in[0];
    const float* Wk = (const float*)d_in[1];
    const float* Wv = (const float*)d_in[2];
    const float* Wq = (const float*)d_in[3];
    const float* Wp = (const float*)d_in[4];
    const float* bp = (const float*)d_in[5];
    float* out = (float*)d_out;

    float *qkvb, *yb;
    cudaGetSymbolAddress((void**)&qkvb, g_qkv);
    cudaGetSymbolAddress((void**)&yb, g_y);

    // Fused qkv projection with inline weight concat: [4096,1152]
    gemm_tc<false, true><<<dim3(9, 32), 256>>>(x, Wq, Wk, Wv, nullptr, qkvb, NQKV, 1024);
    // attention -> y [B,T,C] (head-transposed layout baked in)
    attn_tc<<<512, 256>>>(qkvb, yb);
    // out = y @ Wp.T + bp
    gemm_tc<true, false><<<dim3(8, 32), 256>>>(yb, Wp, nullptr, nullptr, bp, out, 1024, 1024);
}

// round 6
// speedup vs baseline: 2.4573x; 1.0897x over previous
#include <cuda_runtime.h>
#include <math.h>
#include <stdint.h>

#define B_ 2
#define T_ 2048
#define C_ 1024
#define H_ 16
#define HS_ 64
#define NQKV 1152  // 1024 q + 64 k + 64 v

// Scratch (allocation-free rule: __device__ globals)
__device__ float g_qkv[B_ * T_ * NQKV];    // fused projection output (k/v cols pre-tf32)
__device__ float g_y[B_ * T_ * C_];

__device__ __forceinline__ uint32_t f2tf(float f) {
    uint32_t u;
    asm("cvt.rna.tf32.f32 %0, %1;" : "=r"(u) : "f"(f));
    return u;
}

__device__ __forceinline__ uint32_t smaddr(const void* p) {
    return (uint32_t)__cvta_generic_to_shared(p);
}

__device__ __forceinline__ void cp16(uint32_t s, const void* g) {
    asm volatile("cp.async.cg.shared.global [%0], [%1], 16;" :: "r"(s), "l"(g));
}

__device__ __forceinline__ void mma_tf32(float c[4], const uint32_t* a, const uint32_t* b) {
    asm volatile(
        "mma.sync.aligned.m16n8k8.row.col.f32.tf32.tf32.f32 "
        "{%0,%1,%2,%3}, {%4,%5,%6,%7}, {%8,%9}, {%0,%1,%2,%3};"
        : "+f"(c[0]), "+f"(c[1]), "+f"(c[2]), "+f"(c[3])
        : "r"(a[0]), "r"(a[1]), "r"(a[2]), "r"(a[3]), "r"(b[0]), "r"(b[1]));
}

// C[m,n] = sum_k A[m,k] * W[n,k] (+bias), tf32 tensor cores.
// BM=128, BK=32, BN=128. 256 threads = 8 warps (4m x 2n).
// Double-buffered smem (dynamic, 73728B), register prefetch, ONE barrier per K-iter.
// QKV=true: W = virtual concat Wq(1024)‖Wk(64)‖Wv(64); k/v output cols stored as tf32 bits.
template <bool BIAS, bool QKV>
__global__ __launch_bounds__(256) void gemm_tc(const float* __restrict__ A,
                                               const float* __restrict__ Wq,
                                               const float* __restrict__ Wk,
                                               const float* __restrict__ Wv,
                                               const float* __restrict__ bias,
                                               float* __restrict__ C,
                                               int N, int K) {
    extern __shared__ __align__(16) uint32_t smp[];
    // layout: As0 | As1 | Bs0 | Bs1, each 128*36 words
    const int ASZ = 128 * 36;
    int tid = threadIdx.x, lane = tid & 31, warp = tid >> 5;
    int g = lane >> 2, q4 = lane & 3;
    int wm = warp & 3, wn = warp >> 2;
    int bm = blockIdx.y * 128, bn = blockIdx.x * 128;
    int lr = tid >> 3, lc4 = (tid & 7) * 4;

    float acc[2][8][4];
#pragma unroll
    for (int mt = 0; mt < 2; mt++)
#pragma unroll
        for (int j = 0; j < 8; j++)
#pragma unroll
            for (int e = 0; e < 4; e++) acc[mt][j][e] = 0.f;

    const float* arow[4];
    const float* wrow[4];
#pragma unroll
    for (int t = 0; t < 4; t++) {
        int ra = bm + lr + 32 * t;
        arow[t] = A + (size_t)ra * K + lc4;
        int rw = bn + lr + 32 * t;
        if (QKV)
            wrow[t] = (rw < 1024 ? Wq + (size_t)rw * K
                     : rw < 1088 ? Wk + (size_t)(rw - 1024) * K
                                 : Wv + (size_t)(rw - 1088) * K) + lc4;
        else
            wrow[t] = Wq + (size_t)rw * K + lc4;
    }

    float4 pa[4], pb[4];
#pragma unroll
    for (int t = 0; t < 4; t++) {
        pa[t] = *(const float4*)(arow[t]);
        pb[t] = *(const float4*)(wrow[t]);
    }
    // store tile 0 into buffer 0
#pragma unroll
    for (int t = 0; t < 4; t++) {
        *(uint4*)&smp[(lr + t * 32) * 36 + lc4] =
            make_uint4(f2tf(pa[t].x), f2tf(pa[t].y), f2tf(pa[t].z), f2tf(pa[t].w));
        *(uint4*)&smp[2 * ASZ + (lr + t * 32) * 36 + lc4] =
            make_uint4(f2tf(pb[t].x), f2tf(pb[t].y), f2tf(pb[t].z), f2tf(pb[t].w));
    }
    __syncthreads();

    for (int k0 = 0; k0 < K; k0 += 32) {
        int cur = (k0 >> 5) & 1;
        bool more = (k0 + 32) < K;
        if (more) {
#pragma unroll
            for (int t = 0; t < 4; t++) {
                pa[t] = *(const float4*)(arow[t] + k0 + 32);
                pb[t] = *(const float4*)(wrow[t] + k0 + 32);
            }
        }
        const uint32_t* Asb = smp + cur * ASZ;
        const uint32_t* Bsb = smp + 2 * ASZ + cur * ASZ;
#pragma unroll
        for (int kk = 0; kk < 4; kk++) {
            uint32_t af[2][4], bf[8][2];
#pragma unroll
            for (int mt = 0; mt < 2; mt++) {
                int rb = wm * 32 + mt * 16;
                af[mt][0] = Asb[(rb + g) * 36 + kk * 8 + q4];
                af[mt][1] = Asb[(rb + g + 8) * 36 + kk * 8 + q4];
                af[mt][2] = Asb[(rb + g) * 36 + kk * 8 + q4 + 4];
                af[mt][3] = Asb[(rb + g + 8) * 36 + kk * 8 + q4 + 4];
            }
#pragma unroll
            for (int j = 0; j < 8; j++) {
                int nb = wn * 64 + j * 8 + g;
                bf[j][0] = Bsb[nb * 36 + kk * 8 + q4];
                bf[j][1] = Bsb[nb * 36 + kk * 8 + q4 + 4];
            }
#pragma unroll
            for (int mt = 0; mt < 2; mt++)
#pragma unroll
                for (int j = 0; j < 8; j++) mma_tf32(acc[mt][j], af[mt], bf[j]);
        }
        if (more) {
            uint32_t* Asn = smp + (1 - cur) * ASZ;
            uint32_t* Bsn = smp + 2 * ASZ + (1 - cur) * ASZ;
#pragma unroll
            for (int t = 0; t < 4; t++) {
                *(uint4*)&Asn[(lr + t * 32) * 36 + lc4] =
                    make_uint4(f2tf(pa[t].x), f2tf(pa[t].y), f2tf(pa[t].z), f2tf(pa[t].w));
                *(uint4*)&Bsn[(lr + t * 32) * 36 + lc4] =
                    make_uint4(f2tf(pb[t].x), f2tf(pb[t].y), f2tf(pb[t].z), f2tf(pb[t].w));
            }
            __syncthreads();
        }
    }

#pragma unroll
    for (int mt = 0; mt < 2; mt++)
#pragma unroll
        for (int j = 0; j < 8; j++) {
            int row = bm + wm * 32 + mt * 16 + g;
            int col = bn + wn * 64 + j * 8 + 2 * q4;
            float2 v0 = make_float2(acc[mt][j][0], acc[mt][j][1]);
            float2 v1 = make_float2(acc[mt][j][2], acc[mt][j][3]);
            if (BIAS) {
                float b0 = bias[col], b1 = bias[col + 1];
                v0.x += b0; v0.y += b1; v1.x += b0; v1.y += b1;
            }
            if (QKV && col >= 1024) {  // k/v region: store tf32 bits (pre-converted for attn)
                v0.x = __uint_as_float(f2tf(v0.x));
                v0.y = __uint_as_float(f2tf(v0.y));
                v1.x = __uint_as_float(f2tf(v1.x));
                v1.y = __uint_as_float(f2tf(v1.y));
            }
            *(float2*)&C[(size_t)row * N + col] = v0;
            *(float2*)&C[(size_t)(row + 8) * N + col] = v1;
        }
}

// Flash-style causal MQA attention, tf32 tensor cores.
// 256 thr = 8 warps; each warp owns 16 query rows. 64-key tiles from fused qkv buffer.
// K/V arrive pre-converted to tf32 bits -> staging is pure cp.async, double-buffered.
// q remap quirk: q[b,h,t,:] = qkv[b, h*128 + t/16, (t%16)*64 .. +64).
__global__ __launch_bounds__(256, 2) void attn_tc(const float* __restrict__ qkv,
                                                  float* __restrict__ y) {
    extern __shared__ __align__(16) uint32_t smp[];
    // layout: Ks0 | Ks1 (64*68 each) | Vs0 | Vs1 (64*72 each)
    const int KSZ = 64 * 68, VSZ = 64 * 72;
    int bid = blockIdx.x;
    int qt = 15 - (bid >> 5);  // longest blocks first (LPT)
    int bh = bid & 31;
    int b = bh >> 4, h = bh & 15;
    int tid = threadIdx.x, lane = tid & 31, warp = tid >> 5;
    int g = lane >> 2, q4 = lane & 3;
    int r0 = qt * 128 + warp * 16 + g;
    int r1 = r0 + 8;

    const float* base = qkv + (size_t)b * T_ * NQKV;

    // staging constants (per thread: 4 K rows + 4 V rows, 16B each)
    int sr = tid >> 4, sc4 = (tid & 15) * 4;

    // Q fragments (remapped), pre-scaled by hs^-0.5 = 0.125
    uint32_t qa[8][4];
#pragma unroll
    for (int kk = 0; kk < 8; kk++) {
        int c0 = kk * 8 + q4;
        size_t a0 = (size_t)(h * 128 + (r0 >> 4)) * NQKV + (r0 & 15) * 64;
        size_t a1 = (size_t)(h * 128 + (r1 >> 4)) * NQKV + (r1 & 15) * 64;
        qa[kk][0] = f2tf(0.125f * base[a0 + c0]);
        qa[kk][1] = f2tf(0.125f * base[a1 + c0]);
        qa[kk][2] = f2tf(0.125f * base[a0 + c0 + 4]);
        qa[kk][3] = f2tf(0.125f * base[a1 + c0 + 4]);
    }

    float o[8][4];
#pragma unroll
    for (int j = 0; j < 8; j++)
#pragma unroll
        for (int e = 0; e < 4; e++) o[j][e] = 0.f;
    float m0 = -INFINITY, m1 = -INFINITY, l0 = 0.f, l1 = 0.f;

    int nkt = qt * 2 + 2;
    int wrmin = qt * 128 + warp * 16;
    int wrmax = wrmin + 15;
    int srcA = (lane & ~3) | (q4 >> 1);
    int srcB = srcA + 2;
    bool sel = (q4 & 1) != 0;

    // stage tile kt into buffer bi (pure 16B async copies; data already tf32 bits)
    auto stage = [&](int kt, int bi) {
#pragma unroll
        for (int t = 0; t < 4; t++) {
            int r = sr + t * 16;
            size_t row = (size_t)(kt * 64 + r) * NQKV;
            cp16(smaddr(&smp[bi * KSZ + r * 68 + sc4]), &base[row + 1024 + sc4]);
            cp16(smaddr(&smp[2 * KSZ + bi * VSZ + r * 72 + sc4]), &base[row + 1088 + sc4]);
        }
        asm volatile("cp.async.commit_group;");
    };

    stage(0, 0);

    for (int kt = 0; kt < nkt; kt++) {
        if (kt + 1 < nkt) {
            stage(kt + 1, (kt + 1) & 1);
            asm volatile("cp.async.wait_group 1;");
        } else {
            asm volatile("cp.async.wait_group 0;");
        }
        __syncthreads();

        int ktb = kt * 64;
        if (ktb <= wrmax) {
            const uint32_t* Kc = smp + (kt & 1) * KSZ;
            const uint32_t* Vc = smp + 2 * KSZ + (kt & 1) * VSZ;

            // S = Q K^T (pre-scaled)
            float s[8][4];
#pragma unroll
            for (int j = 0; j < 8; j++)
#pragma unroll
                for (int e = 0; e < 4; e++) s[j][e] = 0.f;
#pragma unroll
            for (int kk = 0; kk < 8; kk++) {
#pragma unroll
                for (int j = 0; j < 8; j++) {
                    uint32_t bf[2];
                    bf[0] = Kc[(j * 8 + g) * 68 + kk * 8 + q4];
                    bf[1] = Kc[(j * 8 + g) * 68 + kk * 8 + q4 + 4];
                    mma_tf32(s[j], qa[kk], bf);
                }
            }

            // mask + online softmax (s reused as float probabilities)
            bool needmask = (ktb + 63) > wrmin;
            float t0 = -INFINITY, t1 = -INFINITY;
#pragma unroll
            for (int j = 0; j < 8; j++) {
                if (needmask) {
                    int tk = ktb + j * 8 + 2 * q4;
                    if (tk > r0) s[j][0] = -INFINITY;
                    if (tk + 1 > r0) s[j][1] = -INFINITY;
                    if (tk > r1) s[j][2] = -INFINITY;
                    if (tk + 1 > r1) s[j][3] = -INFINITY;
                }
                t0 = fmaxf(t0, fmaxf(s[j][0], s[j][1]));
                t1 = fmaxf(t1, fmaxf(s[j][2], s[j][3]));
            }
            t0 = fmaxf(t0, __shfl_xor_sync(0xffffffffu, t0, 1));
            t0 = fmaxf(t0, __shfl_xor_sync(0xffffffffu, t0, 2));
            t1 = fmaxf(t1, __shfl_xor_sync(0xffffffffu, t1, 1));
            t1 = fmaxf(t1, __shfl_xor_sync(0xffffffffu, t1, 2));
            float mn0 = fmaxf(m0, t0), mn1 = fmaxf(m1, t1);
            float cr0 = __expf(m0 - mn0), cr1 = __expf(m1 - mn1);
            m0 = mn0; m1 = mn1;
            l0 *= cr0; l1 *= cr1;
#pragma unroll
            for (int j = 0; j < 8; j++) {
                o[j][0] *= cr0; o[j][1] *= cr0;
                o[j][2] *= cr1; o[j][3] *= cr1;
            }
#pragma unroll
            for (int j = 0; j < 8; j++) {
                s[j][0] = __expf(s[j][0] - m0);
                s[j][1] = __expf(s[j][1] - m0);
                s[j][2] = __expf(s[j][2] - m1);
                s[j][3] = __expf(s[j][3] - m1);
                l0 += s[j][0] + s[j][1];
                l1 += s[j][2] + s[j][3];
            }

            // O += P V  (C-frag floats -> A-frag via quad shuffles, convert post-select)
#pragma unroll
            for (int kk = 0; kk < 8; kk++) {
                float x0 = __shfl_sync(0xffffffffu, s[kk][0], srcA);
                float x1 = __shfl_sync(0xffffffffu, s[kk][1], srcA);
                float x2 = __shfl_sync(0xffffffffu, s[kk][2], srcA);
                float x3 = __shfl_sync(0xffffffffu, s[kk][3], srcA);
                float y0 = __shfl_sync(0xffffffffu, s[kk][0], srcB);
                float y1 = __shfl_sync(0xffffffffu, s[kk][1], srcB);
                float y2 = __shfl_sync(0xffffffffu, s[kk][2], srcB);
                float y3 = __shfl_sync(0xffffffffu, s[kk][3], srcB);
                uint32_t pa[4];
                pa[0] = f2tf(sel ? x1 : x0);
                pa[1] = f2tf(sel ? x3 : x2);
                pa[2] = f2tf(sel ? y1 : y0);
                pa[3] = f2tf(sel ? y3 : y2);
#pragma unroll
                for (int j = 0; j < 8; j++) {
                    uint32_t bf[2];
                    bf[0] = Vc[(kk * 8 + q4) * 72 + j * 8 + g];
                    bf[1] = Vc[(kk * 8 + q4 + 4) * 72 + j * 8 + g];
                    mma_tf32(o[j], pa, bf);
                }
            }
        }
        __syncthreads();
    }

    l0 += __shfl_xor_sync(0xffffffffu, l0, 1);
    l0 += __shfl_xor_sync(0xffffffffu, l0, 2);
    l1 += __shfl_xor_sync(0xffffffffu, l1, 1);
    l1 += __shfl_xor_sync(0xffffffffu, l1, 2);
    float i0 = 1.f / l0, i1 = 1.f / l1;
    float* yb = y + (size_t)b * T_ * C_;
#pragma unroll
    for (int j = 0; j < 8; j++) {
        int col = h * 64 + j * 8 + 2 * q4;
        *(float2*)&yb[(size_t)r0 * C_ + col] = make_float2(o[j][0] * i0, o[j][1] * i0);
        *(float2*)&yb[(size_t)r1 * C_ + col] = make_float2(o[j][2] * i1, o[j][3] * i1);
    }
}

extern "C" void kernel_launch(void* const* d_in, const int* in_sizes, int n_in,
                              void* d_out, int out_size) {
    (void)in_sizes; (void)n_in; (void)out_size;
    const float* x  = (const float*)d_in[0];
    const float* Wk = (const float*)d_in[1];
    const float* Wv = (const float*)d_in[2];
    const float* Wq = (const float*)d_in[3];
    const float* Wp = (const float*)d_in[4];
    const float* bp = (const float*)d_in[5];
    float* out = (float*)d_out;

    float *qkvb, *yb;
    cudaGetSymbolAddress((void**)&qkvb, g_qkv);
    cudaGetSymbolAddress((void**)&yb, g_y);

    const int GEMM_SMEM = 4 * 128 * 36 * 4;             // 73728 B
    const int ATTN_SMEM = (2 * 64 * 68 + 2 * 64 * 72) * 4;  // 71680 B
    cudaFuncSetAttribute(gemm_tc<false, true>,
                         cudaFuncAttributeMaxDynamicSharedMemorySize, GEMM_SMEM);
    cudaFuncSetAttribute(gemm_tc<true, false>,
                         cudaFuncAttributeMaxDynamicSharedMemorySize, GEMM_SMEM);
    cudaFuncSetAttribute(attn_tc,
                         cudaFuncAttributeMaxDynamicSharedMemorySize, ATTN_SMEM);

    // Fused qkv projection with inline weight concat: [4096,1152]; k/v cols -> tf32 bits
    gemm_tc<false, true><<<dim3(9, 32), 256, GEMM_SMEM>>>(x, Wq, Wk, Wv, nullptr, qkvb,
                                                          NQKV, 1024);
    // attention -> y [B,T,C] (head-transposed layout baked in)
    attn_tc<<<512, 256, ATTN_SMEM>>>(qkvb, yb);
    // out = y @ Wp.T + bp
    gemm_tc<true, false><<<dim3(8, 32), 256, GEMM_SMEM>>>(yb, Wp, nullptr, nullptr, bp, out,
                                                          1024, 1024);
}